// round 7
// baseline (speedup 1.0000x reference)
#include <cuda_runtime.h>
#include <cuda_bf16.h>
#include <math.h>
#include <float.h>

#define D    1024
#define H    16
#define HD   64
#define DFF  4096
#define LYR  4
#define SEQ  1024
#define VOC  32000
#define EPSF 1e-5f
#define NEGF (-3.0e38f)

// ---------------- scratch (device globals; no runtime allocation) ----------
__device__ float g_x  [SEQ * D];
__device__ float g_ex [SEQ * D];
__device__ float g_nrm[SEQ * D];
__device__ float g_q  [SEQ * D];
__device__ float g_k  [SEQ * D];
__device__ float g_v  [SEQ * D];
__device__ float g_y  [SEQ * D];
__device__ float g_h1 [SEQ * DFF];
__device__ float g_h2 [SEQ * DFF];

// ---------------- helpers ---------------------------------------------------
__device__ __forceinline__ float blockReduce256(float v) {
    __shared__ float sh[8];
    __shared__ float tot;
    int lane = threadIdx.x & 31, wid = threadIdx.x >> 5;
#pragma unroll
    for (int o = 16; o; o >>= 1) v += __shfl_xor_sync(0xffffffffu, v, o);
    if (lane == 0) sh[wid] = v;
    __syncthreads();
    if (wid == 0) {
        float t = (lane < 8) ? sh[lane] : 0.f;
#pragma unroll
        for (int o = 4; o; o >>= 1) t += __shfl_xor_sync(0xffffffffu, t, o);
        if (lane == 0) tot = t;
    }
    __syncthreads();
    return tot;
}

// ---------------- embed gather + rms ---------------------------------------
// grid = SEQ blocks, 256 threads; each thread handles one float4 (D=1024)
__global__ void embed_rms_kernel(const int* __restrict__ ids,
                                 const float* __restrict__ emb,
                                 float* __restrict__ x, float* __restrict__ ex) {
    int row = blockIdx.x;
    int id  = ids[row];
    float4 v = ((const float4*)(emb + (size_t)id * D))[threadIdx.x];
    float ss = v.x*v.x + v.y*v.y + v.z*v.z + v.w*v.w;
    ss = blockReduce256(ss);
    float r = rsqrtf(ss * (1.0f / D) + EPSF);
    float4 o = make_float4(v.x*r, v.y*r, v.z*r, v.w*r);
    ((float4*)(x  + (size_t)row * D))[threadIdx.x] = o;
    ((float4*)(ex + (size_t)row * D))[threadIdx.x] = o;
}

// ---------------- rmsnorm (row-wise over D) ---------------------------------
__global__ void rmsnorm_kernel(const float* __restrict__ in, float* __restrict__ out) {
    int row = blockIdx.x;
    float4 v = ((const float4*)(in + (size_t)row * D))[threadIdx.x];
    float ss = v.x*v.x + v.y*v.y + v.z*v.z + v.w*v.w;
    ss = blockReduce256(ss);
    float r = rsqrtf(ss * (1.0f / D) + EPSF);
    float4 o = make_float4(v.x*r, v.y*r, v.z*r, v.w*r);
    ((float4*)(out + (size_t)row * D))[threadIdx.x] = o;
}

// ---------------- RoPE + per-head rms (+optional head_gain), in place -------
// grid = (SEQ, H), 64 threads
__global__ void rope_rms_kernel(float* __restrict__ vec,
                                const float* __restrict__ gain, int l) {
    int s = blockIdx.x, h = blockIdx.y;
    int t = threadIdx.x;
    __shared__ float buf[HD];
    __shared__ float red[2];
    float* p = vec + (size_t)s * D + h * HD;
    buf[t] = p[t];
    __syncthreads();
    int j = t & 31;
    double inv = pow(10000.0, -(double)j / 32.0);
    double ang = (double)s * inv;
    float c  = (float)cos(ang);
    float sn = (float)sin(ang);
    float o;
    if (t < 32) o =  buf[t] * c      + buf[t + 32] * sn;
    else        o = -buf[t - 32] * sn + buf[t] * c;
    float ss = o * o;
#pragma unroll
    for (int off = 16; off; off >>= 1) ss += __shfl_xor_sync(0xffffffffu, ss, off);
    if ((t & 31) == 0) red[t >> 5] = ss;
    __syncthreads();
    float tot = red[0] + red[1];
    float r = rsqrtf(tot * (1.0f / HD) + EPSF);
    float g = gain ? gain[l * H + h] : 1.0f;
    p[t] = o * r * g;
}

// ---------------- SGEMM: C = res + gain * (A @ B^T) -------------------------
// A: MxK row-major, B: NxK row-major. 128x128 tile, BK=8, 256 thr, 8x8/thread.
// M,N multiples of 128; K multiple of 8 (all shapes here qualify).
__global__ void __launch_bounds__(256)
sgemm_kernel(const float* __restrict__ A, const float* __restrict__ B,
             float* __restrict__ C, int M, int N, int K,
             const float* __restrict__ res, const float* __restrict__ gainPtr) {
    __shared__ float As[8][128];
    __shared__ float Bs[8][128];
    int tid = threadIdx.x;
    int tx = tid & 15, ty = tid >> 4;
    const float* Ab = A + (size_t)blockIdx.y * 128 * K;
    const float* Bb = B + (size_t)blockIdx.x * 128 * K;
    int lr = tid >> 1;
    int lc = (tid & 1) << 2;
    float acc[8][8];
#pragma unroll
    for (int i = 0; i < 8; i++)
#pragma unroll
        for (int jj = 0; jj < 8; jj++) acc[i][jj] = 0.f;

    for (int k0 = 0; k0 < K; k0 += 8) {
        float4 a4 = *(const float4*)(Ab + (size_t)lr * K + k0 + lc);
        float4 b4 = *(const float4*)(Bb + (size_t)lr * K + k0 + lc);
        As[lc + 0][lr] = a4.x; As[lc + 1][lr] = a4.y; As[lc + 2][lr] = a4.z; As[lc + 3][lr] = a4.w;
        Bs[lc + 0][lr] = b4.x; Bs[lc + 1][lr] = b4.y; Bs[lc + 2][lr] = b4.z; Bs[lc + 3][lr] = b4.w;
        __syncthreads();
#pragma unroll
        for (int kk = 0; kk < 8; kk++) {
            float4 a0 = *(const float4*)&As[kk][ty << 3];
            float4 a1 = *(const float4*)&As[kk][(ty << 3) + 4];
            float4 b0 = *(const float4*)&Bs[kk][tx << 3];
            float4 b1 = *(const float4*)&Bs[kk][(tx << 3) + 4];
            float ar[8] = {a0.x, a0.y, a0.z, a0.w, a1.x, a1.y, a1.z, a1.w};
            float br[8] = {b0.x, b0.y, b0.z, b0.w, b1.x, b1.y, b1.z, b1.w};
#pragma unroll
            for (int i = 0; i < 8; i++)
#pragma unroll
                for (int jj = 0; jj < 8; jj++)
                    acc[i][jj] = fmaf(ar[i], br[jj], acc[i][jj]);
        }
        __syncthreads();
    }
    float g = gainPtr ? *gainPtr : 1.0f;
    int r0 = blockIdx.y * 128 + (ty << 3);
    int c0 = blockIdx.x * 128 + (tx << 3);
#pragma unroll
    for (int i = 0; i < 8; i++) {
        size_t base = (size_t)(r0 + i) * N + c0;
        float4 v0 = make_float4(g * acc[i][0], g * acc[i][1], g * acc[i][2], g * acc[i][3]);
        float4 v1 = make_float4(g * acc[i][4], g * acc[i][5], g * acc[i][6], g * acc[i][7]);
        if (res) {
            float4 r4a = *(const float4*)(res + base);
            float4 r4b = *(const float4*)(res + base + 4);
            v0.x += r4a.x; v0.y += r4a.y; v0.z += r4a.z; v0.w += r4a.w;
            v1.x += r4b.x; v1.y += r4b.y; v1.z += r4b.z; v1.w += r4b.w;
        }
        *(float4*)(C + base)     = v0;
        *(float4*)(C + base + 4) = v1;
    }
}

// ---------------- fused causal attention (online softmax) -------------------
// grid = (H, SEQ/64), 256 threads. Q tile 64 rows, K/V tiles of 32.
__global__ void __launch_bounds__(256)
attn_kernel(const float* __restrict__ q, const float* __restrict__ k,
            const float* __restrict__ v, float* __restrict__ y) {
    const int h  = blockIdx.x;
    const int q0 = blockIdx.y * 64;
    __shared__ float Qs[64][64];     // [d][q]
    __shared__ float Ks[64][32];     // [d][k]
    __shared__ float Vs[32][64];     // [k][d]
    __shared__ float Ss[64][33];     // scores/probs, padded
    __shared__ float mS[64], lS[64], aS[64];
    int tid = threadIdx.x;
    int tx = tid & 15, ty = tid >> 4;

    {   // load Q tile (transposed into smem)
        int r  = tid >> 2;
        int d0 = (tid & 3) << 4;
        const float* src = q + (size_t)(q0 + r) * D + h * HD + d0;
#pragma unroll
        for (int i = 0; i < 16; i += 4) {
            float4 t4 = *(const float4*)(src + i);
            Qs[d0 + i + 0][r] = t4.x; Qs[d0 + i + 1][r] = t4.y;
            Qs[d0 + i + 2][r] = t4.z; Qs[d0 + i + 3][r] = t4.w;
        }
    }
    if (tid < 64) { mS[tid] = NEGF; lS[tid] = 0.f; }
    float acc[4][4];
#pragma unroll
    for (int i = 0; i < 4; i++)
#pragma unroll
        for (int jj = 0; jj < 4; jj++) acc[i][jj] = 0.f;
    __syncthreads();

    const int nk = q0 + 64;
    for (int k0 = 0; k0 < nk; k0 += 32) {
        {   // load K (transposed) and V tiles
            int kr = tid >> 3;
            int d0 = (tid & 7) << 3;
            const float* ks = k + (size_t)(k0 + kr) * D + h * HD + d0;
            float4 t0 = *(const float4*)ks;
            float4 t1 = *(const float4*)(ks + 4);
            Ks[d0 + 0][kr] = t0.x; Ks[d0 + 1][kr] = t0.y; Ks[d0 + 2][kr] = t0.z; Ks[d0 + 3][kr] = t0.w;
            Ks[d0 + 4][kr] = t1.x; Ks[d0 + 5][kr] = t1.y; Ks[d0 + 6][kr] = t1.z; Ks[d0 + 7][kr] = t1.w;
            const float* vsp = v + (size_t)(k0 + kr) * D + h * HD + d0;
            *(float4*)&Vs[kr][d0]     = *(const float4*)vsp;
            *(float4*)&Vs[kr][d0 + 4] = *(const float4*)(vsp + 4);
        }
        __syncthreads();

        // scores: each thread 4 q-rows x 2 k-cols
        float sc[4][2];
#pragma unroll
        for (int i = 0; i < 4; i++) { sc[i][0] = 0.f; sc[i][1] = 0.f; }
#pragma unroll 16
        for (int d = 0; d < 64; d++) {
            float4 qa = *(const float4*)&Qs[d][ty << 2];
            float2 kb = *(const float2*)&Ks[d][tx << 1];
            sc[0][0] = fmaf(qa.x, kb.x, sc[0][0]); sc[0][1] = fmaf(qa.x, kb.y, sc[0][1]);
            sc[1][0] = fmaf(qa.y, kb.x, sc[1][0]); sc[1][1] = fmaf(qa.y, kb.y, sc[1][1]);
            sc[2][0] = fmaf(qa.z, kb.x, sc[2][0]); sc[2][1] = fmaf(qa.z, kb.y, sc[2][1]);
            sc[3][0] = fmaf(qa.w, kb.x, sc[3][0]); sc[3][1] = fmaf(qa.w, kb.y, sc[3][1]);
        }
#pragma unroll
        for (int i = 0; i < 4; i++) {
            int qg = q0 + (ty << 2) + i;
#pragma unroll
            for (int jj = 0; jj < 2; jj++) {
                int kg = k0 + (tx << 1) + jj;
                float val = sc[i][jj] * 0.125f;   // HD^-0.5
                if (kg > qg) val = NEGF;
                Ss[(ty << 2) + i][(tx << 1) + jj] = val;
            }
        }
        __syncthreads();

        // online softmax update (one thread per q row)
        if (tid < 64) {
            float mo = mS[tid];
            float mx = mo;
#pragma unroll
            for (int jj = 0; jj < 32; jj++) mx = fmaxf(mx, Ss[tid][jj]);
            float al = expf(mo - mx);
            float sum = 0.f;
#pragma unroll
            for (int jj = 0; jj < 32; jj++) {
                float pp = expf(Ss[tid][jj] - mx);
                Ss[tid][jj] = pp;
                sum += pp;
            }
            lS[tid] = lS[tid] * al + sum;
            mS[tid] = mx;
            aS[tid] = al;
        }
        __syncthreads();

        // rescale accumulators, then P @ V
#pragma unroll
        for (int i = 0; i < 4; i++) {
            float al = aS[(ty << 2) + i];
#pragma unroll
            for (int jj = 0; jj < 4; jj++) acc[i][jj] *= al;
        }
#pragma unroll 8
        for (int kk = 0; kk < 32; kk++) {
            float4 vb = *(const float4*)&Vs[kk][tx << 2];
            float p0 = Ss[(ty << 2) + 0][kk];
            float p1 = Ss[(ty << 2) + 1][kk];
            float p2 = Ss[(ty << 2) + 2][kk];
            float p3 = Ss[(ty << 2) + 3][kk];
            acc[0][0] = fmaf(p0, vb.x, acc[0][0]); acc[0][1] = fmaf(p0, vb.y, acc[0][1]);
            acc[0][2] = fmaf(p0, vb.z, acc[0][2]); acc[0][3] = fmaf(p0, vb.w, acc[0][3]);
            acc[1][0] = fmaf(p1, vb.x, acc[1][0]); acc[1][1] = fmaf(p1, vb.y, acc[1][1]);
            acc[1][2] = fmaf(p1, vb.z, acc[1][2]); acc[1][3] = fmaf(p1, vb.w, acc[1][3]);
            acc[2][0] = fmaf(p2, vb.x, acc[2][0]); acc[2][1] = fmaf(p2, vb.y, acc[2][1]);
            acc[2][2] = fmaf(p2, vb.z, acc[2][2]); acc[2][3] = fmaf(p2, vb.w, acc[2][3]);
            acc[3][0] = fmaf(p3, vb.x, acc[3][0]); acc[3][1] = fmaf(p3, vb.y, acc[3][1]);
            acc[3][2] = fmaf(p3, vb.z, acc[3][2]); acc[3][3] = fmaf(p3, vb.w, acc[3][3]);
        }
        __syncthreads();
    }

#pragma unroll
    for (int i = 0; i < 4; i++) {
        float linv = 1.0f / lS[(ty << 2) + i];
        float4 o = make_float4(acc[i][0] * linv, acc[i][1] * linv,
                               acc[i][2] * linv, acc[i][3] * linv);
        *(float4*)(y + (size_t)(q0 + (ty << 2) + i) * D + h * HD + (tx << 2)) = o;
    }
}

// ---------------- elementwise ------------------------------------------------
__global__ void silu_mul_kernel(float* __restrict__ a, const float* __restrict__ b) {
    int i = blockIdx.x * blockDim.x + threadIdx.x;
    float g = a[i];
    float s = 1.0f / (1.0f + expf(-g));
    a[i] = g * s * b[i];
}

__global__ void axpy_kernel(float* __restrict__ x, const float* __restrict__ e,
                            const float* __restrict__ sp) {
    int i = blockIdx.x * blockDim.x + threadIdx.x;
    x[i] = fmaf(e[i], *sp, x[i]);
}

// ---------------- launch -----------------------------------------------------
extern "C" void kernel_launch(void* const* d_in, const int* in_sizes, int n_in,
                              void* d_out, int out_size) {
    const int*   ids          = (const int*)  d_in[0];
    const float* embed        = (const float*)d_in[1];
    const float* Wq           = (const float*)d_in[2];
    const float* Wk           = (const float*)d_in[3];
    const float* Wv           = (const float*)d_in[4];
    const float* Wo           = (const float*)d_in[5];
    const float* head_gain    = (const float*)d_in[6];
    const float* attn_gain    = (const float*)d_in[7];
    const float* Wg           = (const float*)d_in[8];
    const float* Wl           = (const float*)d_in[9];
    const float* Wr           = (const float*)d_in[10];
    const float* mlp_gain     = (const float*)d_in[11];
    const float* embed_skip   = (const float*)d_in[12];
    const float* lm_head      = (const float*)d_in[13];
    const float* lm_head_gain = (const float*)d_in[14];
    float* out = (float*)d_out;

    float *px, *pex, *pn, *pq, *pk, *pv, *py, *ph1, *ph2;
    cudaGetSymbolAddress((void**)&px,  g_x);
    cudaGetSymbolAddress((void**)&pex, g_ex);
    cudaGetSymbolAddress((void**)&pn,  g_nrm);
    cudaGetSymbolAddress((void**)&pq,  g_q);
    cudaGetSymbolAddress((void**)&pk,  g_k);
    cudaGetSymbolAddress((void**)&pv,  g_v);
    cudaGetSymbolAddress((void**)&py,  g_y);
    cudaGetSymbolAddress((void**)&ph1, g_h1);
    cudaGetSymbolAddress((void**)&ph2, g_h2);

    embed_rms_kernel<<<SEQ, 256>>>(ids, embed, px, pex);

    dim3 gDD(D / 128, SEQ / 128);
    dim3 gFF(DFF / 128, SEQ / 128);
    dim3 gRope(SEQ, H);
    dim3 gAttn(H, SEQ / 64);

    for (int l = 0; l < LYR; l++) {
        rmsnorm_kernel<<<SEQ, 256>>>(px, pn);
        sgemm_kernel<<<gDD, 256>>>(pn, Wq + (size_t)l * D * D, pq, SEQ, D, D, nullptr, nullptr);
        sgemm_kernel<<<gDD, 256>>>(pn, Wk + (size_t)l * D * D, pk, SEQ, D, D, nullptr, nullptr);
        sgemm_kernel<<<gDD, 256>>>(pn, Wv + (size_t)l * D * D, pv, SEQ, D, D, nullptr, nullptr);
        rope_rms_kernel<<<gRope, 64>>>(pq, head_gain, l);
        rope_rms_kernel<<<gRope, 64>>>(pk, nullptr, l);
        attn_kernel<<<gAttn, 256>>>(pq, pk, pv, py);
        sgemm_kernel<<<gDD, 256>>>(py, Wo + (size_t)l * D * D, px, SEQ, D, D, px, attn_gain + l);
        rmsnorm_kernel<<<SEQ, 256>>>(px, pn);
        sgemm_kernel<<<gFF, 256>>>(pn, Wg + (size_t)l * DFF * D, ph1, SEQ, DFF, D, nullptr, nullptr);
        sgemm_kernel<<<gFF, 256>>>(pn, Wl + (size_t)l * DFF * D, ph2, SEQ, DFF, D, nullptr, nullptr);
        silu_mul_kernel<<<(SEQ * DFF) / 256, 256>>>(ph1, ph2);
        sgemm_kernel<<<gDD, 256>>>(ph1, Wr + (size_t)l * D * DFF, px, SEQ, D, DFF, px, mlp_gain + l);
        axpy_kernel<<<(SEQ * D) / 256, 256>>>(px, pex, embed_skip + l);
    }

    rmsnorm_kernel<<<SEQ, 256>>>(px, pn);
    sgemm_kernel<<<dim3(VOC / 128, SEQ / 128), 256>>>(pn, lm_head, out,
                                                      SEQ, VOC, D, nullptr, lm_head_gain);
}

// round 8
// speedup vs baseline: 2.1884x; 2.1884x over previous
#include <cuda_runtime.h>
#include <cuda_bf16.h>
#include <math.h>
#include <float.h>
#include <stdint.h>

#define D    1024
#define H    16
#define HD   64
#define DFF  4096
#define LYR  4
#define SEQ  1024
#define VOC  32000
#define EPSF 1e-5f
#define NEGF (-3.0e38f)

// ---------------- scratch (device globals; no runtime allocation) ----------
__device__ float g_x  [SEQ * D];
__device__ float g_ex [SEQ * D];
__device__ float g_nrm[SEQ * D];
__device__ float g_q  [SEQ * D];
__device__ float g_k  [SEQ * D];
__device__ float g_v  [SEQ * D];
__device__ float g_y  [SEQ * D];
__device__ float g_h1 [SEQ * DFF];
__device__ float g_h2 [SEQ * DFF];

// ---------------- helpers ---------------------------------------------------
__device__ __forceinline__ float blockReduce256(float v) {
    __shared__ float sh[8];
    __shared__ float tot;
    int lane = threadIdx.x & 31, wid = threadIdx.x >> 5;
#pragma unroll
    for (int o = 16; o; o >>= 1) v += __shfl_xor_sync(0xffffffffu, v, o);
    if (lane == 0) sh[wid] = v;
    __syncthreads();
    if (wid == 0) {
        float t = (lane < 8) ? sh[lane] : 0.f;
#pragma unroll
        for (int o = 4; o; o >>= 1) t += __shfl_xor_sync(0xffffffffu, t, o);
        if (lane == 0) tot = t;
    }
    __syncthreads();
    return tot;
}

__device__ __forceinline__ uint32_t f2tf(float x) {
    uint32_t r;
    asm("cvt.rna.tf32.f32 %0, %1;" : "=r"(r) : "f"(x));
    return r;
}

__device__ __forceinline__ float4 cvt4(float4 v) {
    float4 o;
    o.x = __uint_as_float(f2tf(v.x));
    o.y = __uint_as_float(f2tf(v.y));
    o.z = __uint_as_float(f2tf(v.z));
    o.w = __uint_as_float(f2tf(v.w));
    return o;
}

__device__ __forceinline__ void mma_tf32(float* c, const uint32_t* a, const uint32_t* b) {
    asm volatile(
        "mma.sync.aligned.m16n8k8.row.col.f32.tf32.tf32.f32 "
        "{%0,%1,%2,%3}, {%4,%5,%6,%7}, {%8,%9}, {%0,%1,%2,%3};"
        : "+f"(c[0]), "+f"(c[1]), "+f"(c[2]), "+f"(c[3])
        : "r"(a[0]), "r"(a[1]), "r"(a[2]), "r"(a[3]), "r"(b[0]), "r"(b[1]));
}

// ---------------- embed gather + rms ---------------------------------------
__global__ void embed_rms_kernel(const int* __restrict__ ids,
                                 const float* __restrict__ emb,
                                 float* __restrict__ x, float* __restrict__ ex) {
    int row = blockIdx.x;
    int id  = ids[row];
    float4 v = ((const float4*)(emb + (size_t)id * D))[threadIdx.x];
    float ss = v.x*v.x + v.y*v.y + v.z*v.z + v.w*v.w;
    ss = blockReduce256(ss);
    float r = rsqrtf(ss * (1.0f / D) + EPSF);
    float4 o = make_float4(v.x*r, v.y*r, v.z*r, v.w*r);
    ((float4*)(x  + (size_t)row * D))[threadIdx.x] = o;
    ((float4*)(ex + (size_t)row * D))[threadIdx.x] = o;
}

// ---------------- rmsnorm (row-wise over D) ---------------------------------
__global__ void rmsnorm_kernel(const float* __restrict__ in, float* __restrict__ out) {
    int row = blockIdx.x;
    float4 v = ((const float4*)(in + (size_t)row * D))[threadIdx.x];
    float ss = v.x*v.x + v.y*v.y + v.z*v.z + v.w*v.w;
    ss = blockReduce256(ss);
    float r = rsqrtf(ss * (1.0f / D) + EPSF);
    float4 o = make_float4(v.x*r, v.y*r, v.z*r, v.w*r);
    ((float4*)(out + (size_t)row * D))[threadIdx.x] = o;
}

// ---------------- RoPE + per-head rms (+optional head_gain), in place -------
__global__ void rope_rms_kernel(float* __restrict__ vec,
                                const float* __restrict__ gain, int l) {
    int s = blockIdx.x, h = blockIdx.y;
    int t = threadIdx.x;
    __shared__ float buf[HD];
    __shared__ float red[2];
    float* p = vec + (size_t)s * D + h * HD;
    buf[t] = p[t];
    __syncthreads();
    int j = t & 31;
    double inv = pow(10000.0, -(double)j / 32.0);
    double ang = (double)s * inv;
    float c  = (float)cos(ang);
    float sn = (float)sin(ang);
    float o;
    if (t < 32) o =  buf[t] * c       + buf[t + 32] * sn;
    else        o = -buf[t - 32] * sn + buf[t] * c;
    float ss = o * o;
#pragma unroll
    for (int off = 16; off; off >>= 1) ss += __shfl_xor_sync(0xffffffffu, ss, off);
    if ((t & 31) == 0) red[t >> 5] = ss;
    __syncthreads();
    float tot = red[0] + red[1];
    float r = rsqrtf(tot * (1.0f / HD) + EPSF);
    float g = gain ? gain[l * H + h] : 1.0f;
    p[t] = o * r * g;
}

// ---------------- TF32 tensor-core GEMM: C = res + gain * (A @ B^T) ---------
// A: MxK row-major fp32, B: NxK row-major fp32. Block 128 x BN, BK=16.
// 256 threads = 8 warps arranged 4(m) x 2(n); warp tile 32 x (BN/2).
// mma.sync.m16n8k8 tf32 with fp32 accumulate. Double-buffered smem, pad-20
// rows (conflict-free for the fragment access pattern).
template <int BN>
__global__ void __launch_bounds__(256)
gemm_tf32_kernel(const float* __restrict__ A, const float* __restrict__ B,
                 float* __restrict__ C, int M, int N, int K,
                 const float* __restrict__ res, const float* __restrict__ gainPtr) {
    constexpr int NT = BN / 16;          // B n-tiles per warp (warp n = BN/2)
    __shared__ float As[2][128][20];
    __shared__ float Bs[2][BN][20];

    const int tid  = threadIdx.x;
    const int warp = tid >> 5;
    const int lane = tid & 31;
    const int wm = warp >> 1;            // 0..3
    const int wn = warp & 1;             // 0..1
    const int r  = lane >> 2;            // 0..7
    const int c  = lane & 3;             // 0..3
    const int mb = wm * 32;
    const int nb = wn * (BN / 2);

    const float* Abase = A + (size_t)blockIdx.y * 128 * K;
    const float* Bbase = B + (size_t)blockIdx.x * BN * K;
    const int lr = tid >> 2;             // 0..63
    const int lc = (tid & 3) << 2;       // 0,4,8,12

    float cacc[2][NT][4];
#pragma unroll
    for (int mt = 0; mt < 2; mt++)
#pragma unroll
        for (int nt = 0; nt < NT; nt++)
#pragma unroll
            for (int i = 0; i < 4; i++) cacc[mt][nt][i] = 0.f;

    const int ntiles = K / 16;

    // preload tile 0
    {
        float4 a0 = *(const float4*)(Abase + (size_t)lr * K + lc);
        float4 a1 = *(const float4*)(Abase + (size_t)(lr + 64) * K + lc);
        *(float4*)&As[0][lr][lc]      = cvt4(a0);
        *(float4*)&As[0][lr + 64][lc] = cvt4(a1);
        float4 b0 = *(const float4*)(Bbase + (size_t)lr * K + lc);
        *(float4*)&Bs[0][lr][lc] = cvt4(b0);
        if (BN == 128) {
            float4 b1 = *(const float4*)(Bbase + (size_t)(lr + 64) * K + lc);
            *(float4*)&Bs[0][lr + 64][lc] = cvt4(b1);
        }
    }
    __syncthreads();

    for (int t = 0; t < ntiles; t++) {
        const int buf = t & 1;
        float4 pa0, pa1, pb0, pb1;
        const bool pf = (t + 1 < ntiles);
        if (pf) {
            const int ko = (t + 1) * 16 + lc;
            pa0 = *(const float4*)(Abase + (size_t)lr * K + ko);
            pa1 = *(const float4*)(Abase + (size_t)(lr + 64) * K + ko);
            pb0 = *(const float4*)(Bbase + (size_t)lr * K + ko);
            if (BN == 128)
                pb1 = *(const float4*)(Bbase + (size_t)(lr + 64) * K + ko);
        }

        const float (*as)[20] = As[buf];
        const float (*bs)[20] = Bs[buf];
#pragma unroll
        for (int ks = 0; ks < 16; ks += 8) {
            uint32_t af[2][4];
#pragma unroll
            for (int mt = 0; mt < 2; mt++) {
                int m0 = mb + mt * 16 + r;
                af[mt][0] = __float_as_uint(as[m0][ks + c]);
                af[mt][1] = __float_as_uint(as[m0 + 8][ks + c]);
                af[mt][2] = __float_as_uint(as[m0][ks + c + 4]);
                af[mt][3] = __float_as_uint(as[m0 + 8][ks + c + 4]);
            }
            uint32_t bfr[NT][2];
#pragma unroll
            for (int nt = 0; nt < NT; nt++) {
                int n0 = nb + nt * 8 + r;
                bfr[nt][0] = __float_as_uint(bs[n0][ks + c]);
                bfr[nt][1] = __float_as_uint(bs[n0][ks + c + 4]);
            }
#pragma unroll
            for (int mt = 0; mt < 2; mt++)
#pragma unroll
                for (int nt = 0; nt < NT; nt++)
                    mma_tf32(cacc[mt][nt], af[mt], bfr[nt]);
        }

        if (pf) {
            const int nbuf = buf ^ 1;
            *(float4*)&As[nbuf][lr][lc]      = cvt4(pa0);
            *(float4*)&As[nbuf][lr + 64][lc] = cvt4(pa1);
            *(float4*)&Bs[nbuf][lr][lc]      = cvt4(pb0);
            if (BN == 128)
                *(float4*)&Bs[nbuf][lr + 64][lc] = cvt4(pb1);
            __syncthreads();
        }
    }

    const float g = gainPtr ? *gainPtr : 1.0f;
#pragma unroll
    for (int mt = 0; mt < 2; mt++) {
        int row0 = blockIdx.y * 128 + mb + mt * 16 + r;
#pragma unroll
        for (int nt = 0; nt < NT; nt++) {
            int col = blockIdx.x * BN + nb + nt * 8 + c * 2;
            size_t i0 = (size_t)row0 * N + col;
            size_t i1 = (size_t)(row0 + 8) * N + col;
            float2 v0 = make_float2(g * cacc[mt][nt][0], g * cacc[mt][nt][1]);
            float2 v1 = make_float2(g * cacc[mt][nt][2], g * cacc[mt][nt][3]);
            if (res) {
                float2 r0 = *(const float2*)(res + i0);
                float2 r1 = *(const float2*)(res + i1);
                v0.x += r0.x; v0.y += r0.y;
                v1.x += r1.x; v1.y += r1.y;
            }
            *(float2*)(C + i0) = v0;
            *(float2*)(C + i1) = v1;
        }
    }
}

// ---------------- fused causal attention (online softmax, exact fp32) -------
__global__ void __launch_bounds__(256)
attn_kernel(const float* __restrict__ q, const float* __restrict__ k,
            const float* __restrict__ v, float* __restrict__ y) {
    const int h  = blockIdx.x;
    const int q0 = blockIdx.y * 64;
    __shared__ float Qs[64][64];     // [d][q]
    __shared__ float Ks[64][32];     // [d][k]
    __shared__ float Vs[32][64];     // [k][d]
    __shared__ float Ss[64][33];
    __shared__ float mS[64], lS[64], aS[64];
    int tid = threadIdx.x;
    int tx = tid & 15, ty = tid >> 4;

    {
        int r  = tid >> 2;
        int d0 = (tid & 3) << 4;
        const float* src = q + (size_t)(q0 + r) * D + h * HD + d0;
#pragma unroll
        for (int i = 0; i < 16; i += 4) {
            float4 t4 = *(const float4*)(src + i);
            Qs[d0 + i + 0][r] = t4.x; Qs[d0 + i + 1][r] = t4.y;
            Qs[d0 + i + 2][r] = t4.z; Qs[d0 + i + 3][r] = t4.w;
        }
    }
    if (tid < 64) { mS[tid] = NEGF; lS[tid] = 0.f; }
    float acc[4][4];
#pragma unroll
    for (int i = 0; i < 4; i++)
#pragma unroll
        for (int jj = 0; jj < 4; jj++) acc[i][jj] = 0.f;
    __syncthreads();

    const int nk = q0 + 64;
    for (int k0 = 0; k0 < nk; k0 += 32) {
        {
            int kr = tid >> 3;
            int d0 = (tid & 7) << 3;
            const float* ks = k + (size_t)(k0 + kr) * D + h * HD + d0;
            float4 t0 = *(const float4*)ks;
            float4 t1 = *(const float4*)(ks + 4);
            Ks[d0 + 0][kr] = t0.x; Ks[d0 + 1][kr] = t0.y; Ks[d0 + 2][kr] = t0.z; Ks[d0 + 3][kr] = t0.w;
            Ks[d0 + 4][kr] = t1.x; Ks[d0 + 5][kr] = t1.y; Ks[d0 + 6][kr] = t1.z; Ks[d0 + 7][kr] = t1.w;
            const float* vsp = v + (size_t)(k0 + kr) * D + h * HD + d0;
            *(float4*)&Vs[kr][d0]     = *(const float4*)vsp;
            *(float4*)&Vs[kr][d0 + 4] = *(const float4*)(vsp + 4);
        }
        __syncthreads();

        float sc[4][2];
#pragma unroll
        for (int i = 0; i < 4; i++) { sc[i][0] = 0.f; sc[i][1] = 0.f; }
#pragma unroll 16
        for (int d = 0; d < 64; d++) {
            float4 qa = *(const float4*)&Qs[d][ty << 2];
            float2 kb = *(const float2*)&Ks[d][tx << 1];
            sc[0][0] = fmaf(qa.x, kb.x, sc[0][0]); sc[0][1] = fmaf(qa.x, kb.y, sc[0][1]);
            sc[1][0] = fmaf(qa.y, kb.x, sc[1][0]); sc[1][1] = fmaf(qa.y, kb.y, sc[1][1]);
            sc[2][0] = fmaf(qa.z, kb.x, sc[2][0]); sc[2][1] = fmaf(qa.z, kb.y, sc[2][1]);
            sc[3][0] = fmaf(qa.w, kb.x, sc[3][0]); sc[3][1] = fmaf(qa.w, kb.y, sc[3][1]);
        }
#pragma unroll
        for (int i = 0; i < 4; i++) {
            int qg = q0 + (ty << 2) + i;
#pragma unroll
            for (int jj = 0; jj < 2; jj++) {
                int kg = k0 + (tx << 1) + jj;
                float val = sc[i][jj] * 0.125f;
                if (kg > qg) val = NEGF;
                Ss[(ty << 2) + i][(tx << 1) + jj] = val;
            }
        }
        __syncthreads();

        if (tid < 64) {
            float mo = mS[tid];
            float mx = mo;
#pragma unroll
            for (int jj = 0; jj < 32; jj++) mx = fmaxf(mx, Ss[tid][jj]);
            float al = expf(mo - mx);
            float sum = 0.f;
#pragma unroll
            for (int jj = 0; jj < 32; jj++) {
                float pp = expf(Ss[tid][jj] - mx);
                Ss[tid][jj] = pp;
                sum += pp;
            }
            lS[tid] = lS[tid] * al + sum;
            mS[tid] = mx;
            aS[tid] = al;
        }
        __syncthreads();

#pragma unroll
        for (int i = 0; i < 4; i++) {
            float al = aS[(ty << 2) + i];
#pragma unroll
            for (int jj = 0; jj < 4; jj++) acc[i][jj] *= al;
        }
#pragma unroll 8
        for (int kk = 0; kk < 32; kk++) {
            float4 vb = *(const float4*)&Vs[kk][tx << 2];
            float p0 = Ss[(ty << 2) + 0][kk];
            float p1 = Ss[(ty << 2) + 1][kk];
            float p2 = Ss[(ty << 2) + 2][kk];
            float p3 = Ss[(ty << 2) + 3][kk];
            acc[0][0] = fmaf(p0, vb.x, acc[0][0]); acc[0][1] = fmaf(p0, vb.y, acc[0][1]);
            acc[0][2] = fmaf(p0, vb.z, acc[0][2]); acc[0][3] = fmaf(p0, vb.w, acc[0][3]);
            acc[1][0] = fmaf(p1, vb.x, acc[1][0]); acc[1][1] = fmaf(p1, vb.y, acc[1][1]);
            acc[1][2] = fmaf(p1, vb.z, acc[1][2]); acc[1][3] = fmaf(p1, vb.w, acc[1][3]);
            acc[2][0] = fmaf(p2, vb.x, acc[2][0]); acc[2][1] = fmaf(p2, vb.y, acc[2][1]);
            acc[2][2] = fmaf(p2, vb.z, acc[2][2]); acc[2][3] = fmaf(p2, vb.w, acc[2][3]);
            acc[3][0] = fmaf(p3, vb.x, acc[3][0]); acc[3][1] = fmaf(p3, vb.y, acc[3][1]);
            acc[3][2] = fmaf(p3, vb.z, acc[3][2]); acc[3][3] = fmaf(p3, vb.w, acc[3][3]);
        }
        __syncthreads();
    }

#pragma unroll
    for (int i = 0; i < 4; i++) {
        float linv = 1.0f / lS[(ty << 2) + i];
        float4 o = make_float4(acc[i][0] * linv, acc[i][1] * linv,
                               acc[i][2] * linv, acc[i][3] * linv);
        *(float4*)(y + (size_t)(q0 + (ty << 2) + i) * D + h * HD + (tx << 2)) = o;
    }
}

// ---------------- elementwise ------------------------------------------------
__global__ void silu_mul_kernel(float* __restrict__ a, const float* __restrict__ b) {
    int i = blockIdx.x * blockDim.x + threadIdx.x;
    float g = a[i];
    float s = 1.0f / (1.0f + expf(-g));
    a[i] = g * s * b[i];
}

__global__ void axpy_kernel(float* __restrict__ x, const float* __restrict__ e,
                            const float* __restrict__ sp) {
    int i = blockIdx.x * blockDim.x + threadIdx.x;
    x[i] = fmaf(e[i], *sp, x[i]);
}

// ---------------- launch -----------------------------------------------------
extern "C" void kernel_launch(void* const* d_in, const int* in_sizes, int n_in,
                              void* d_out, int out_size) {
    const int*   ids          = (const int*)  d_in[0];
    const float* embed        = (const float*)d_in[1];
    const float* Wq           = (const float*)d_in[2];
    const float* Wk           = (const float*)d_in[3];
    const float* Wv           = (const float*)d_in[4];
    const float* Wo           = (const float*)d_in[5];
    const float* head_gain    = (const float*)d_in[6];
    const float* attn_gain    = (const float*)d_in[7];
    const float* Wg           = (const float*)d_in[8];
    const float* Wl           = (const float*)d_in[9];
    const float* Wr           = (const float*)d_in[10];
    const float* mlp_gain     = (const float*)d_in[11];
    const float* embed_skip   = (const float*)d_in[12];
    const float* lm_head      = (const float*)d_in[13];
    const float* lm_head_gain = (const float*)d_in[14];
    float* out = (float*)d_out;

    float *px, *pex, *pn, *pq, *pk, *pv, *py, *ph1, *ph2;
    cudaGetSymbolAddress((void**)&px,  g_x);
    cudaGetSymbolAddress((void**)&pex, g_ex);
    cudaGetSymbolAddress((void**)&pn,  g_nrm);
    cudaGetSymbolAddress((void**)&pq,  g_q);
    cudaGetSymbolAddress((void**)&pk,  g_k);
    cudaGetSymbolAddress((void**)&pv,  g_v);
    cudaGetSymbolAddress((void**)&py,  g_y);
    cudaGetSymbolAddress((void**)&ph1, g_h1);
    cudaGetSymbolAddress((void**)&ph2, g_h2);

    embed_rms_kernel<<<SEQ, 256>>>(ids, embed, px, pex);

    dim3 gDD(D / 64, SEQ / 128);      // BN=64 -> 128 blocks
    dim3 gFF(DFF / 128, SEQ / 128);   // BN=128 -> 256 blocks
    dim3 gRope(SEQ, H);
    dim3 gAttn(H, SEQ / 64);

    for (int l = 0; l < LYR; l++) {
        rmsnorm_kernel<<<SEQ, 256>>>(px, pn);
        gemm_tf32_kernel<64><<<gDD, 256>>>(pn, Wq + (size_t)l * D * D, pq, SEQ, D, D, nullptr, nullptr);
        gemm_tf32_kernel<64><<<gDD, 256>>>(pn, Wk + (size_t)l * D * D, pk, SEQ, D, D, nullptr, nullptr);
        gemm_tf32_kernel<64><<<gDD, 256>>>(pn, Wv + (size_t)l * D * D, pv, SEQ, D, D, nullptr, nullptr);
        rope_rms_kernel<<<gRope, 64>>>(pq, head_gain, l);
        rope_rms_kernel<<<gRope, 64>>>(pk, nullptr, l);
        attn_kernel<<<gAttn, 256>>>(pq, pk, pv, py);
        gemm_tf32_kernel<64><<<gDD, 256>>>(py, Wo + (size_t)l * D * D, px, SEQ, D, D, px, attn_gain + l);
        rmsnorm_kernel<<<SEQ, 256>>>(px, pn);
        gemm_tf32_kernel<128><<<gFF, 256>>>(pn, Wg + (size_t)l * DFF * D, ph1, SEQ, DFF, D, nullptr, nullptr);
        gemm_tf32_kernel<128><<<gFF, 256>>>(pn, Wl + (size_t)l * DFF * D, ph2, SEQ, DFF, D, nullptr, nullptr);
        silu_mul_kernel<<<(SEQ * DFF) / 256, 256>>>(ph1, ph2);
        gemm_tf32_kernel<64><<<gDD, 256>>>(ph1, Wr + (size_t)l * D * DFF, px, SEQ, D, DFF, px, mlp_gain + l);
        axpy_kernel<<<(SEQ * D) / 256, 256>>>(px, pex, embed_skip + l);
    }

    rmsnorm_kernel<<<SEQ, 256>>>(px, pn);
    gemm_tf32_kernel<128><<<dim3(VOC / 128, SEQ / 128), 256>>>(pn, lm_head, out,
                                                               SEQ, VOC, D, nullptr, lm_head_gain);
}